// round 17
// baseline (speedup 1.0000x reference)
#include <cuda_runtime.h>
#include <cuda_fp16.h>
#include <cstdint>

// GlobalPoolDistance: patch-RBF MMD, single fused persistent kernel (R17).
// f16 mma.sync m16n8k16 (f16 accumulate) computes the exp2 argument directly:
//   A row i = [C2*a_0..C2*a_26, 1, -u_i, 0..]   (u = ||a||^2 * log2e/SIG2)
//   B row j = [b_0..b_26,      -v_j, 1, 0..]
//   acc(i,j) = C2*<a,b> - u - v = -log2e*||a-b||^2/SIG2 ; K = exp2(acc).
// Epilogue skip threshold -30 (deterministic per-term bound, see R7);
// diagonal tiles force the epilogue; diagonals replaced by exact 1.0.
// R17 = R16 (chunk-level edge partition) + cross-chunk software pipelining:
// double-buffered A, next-chunk A+B prefetch issued during the current
// chunk's last window, and a depth-2 ticket pipeline published by existing
// window barriers (no dedicated ticket syncs, atomic latency hidden).

#define TILE 128
#define NPATCH 3844
#define NTILES 31
#define NROWS (NTILES * TILE)                     // 3968
#define BATCH 8
#define ROW_U4 4                                  // 64 B per staged row (32 f16)
#define STAGE_U4 (4 * BATCH * NROWS * ROW_U4)
#define CHUNKS 2240        // 960 int-xy + 1152 int-sym + 64 edge-xy + 64 edge-sym
#define WORKERS 296
#define STAGE_TASKS (2 * BATCH * NROWS)           // 63488

// dynamic smem layout
#define SMEM_A_OFF   0                            // 2 x 8 KB A buffers
#define SMEM_B_OFF   16384                        // 8 slots x 8 KB
#define SMEM_RED_OFF (16384 + 8 * 8192)           // 81920
#define SMEM_TKT_OFF (SMEM_RED_OFF + 32)          // 2 x uint
#define SMEM_LST_OFF (SMEM_TKT_OFF + 8)
#define SMEM_BYTES   (SMEM_LST_OFF + 4 + 20)      // 81984

__device__ uint4 g_stage[STAGE_U4];
__device__ float g_partials[WORKERS];
__device__ unsigned int g_bar1;
__device__ unsigned int g_ticket;
__device__ unsigned int g_done;

__device__ __forceinline__ uint32_t smem_to_u32(const void* p) {
    uint32_t a;
    asm("{ .reg .u64 t; cvta.to.shared.u64 t, %1; cvt.u32.u64 %0, t; }"
        : "=r"(a) : "l"(p));
    return a;
}
__device__ __forceinline__ void cp_async16(uint32_t smem, const void* gptr) {
    asm volatile("cp.async.cg.shared.global [%0], [%1], 16;"
                 :: "r"(smem), "l"(gptr) : "memory");
}
#define CP_COMMIT() asm volatile("cp.async.commit_group;" ::: "memory")
#define CP_WAIT0()  asm volatile("cp.async.wait_group 0;" ::: "memory")

__device__ __forceinline__ void ldsm_x4(uint32_t& r0, uint32_t& r1,
                                        uint32_t& r2, uint32_t& r3, uint32_t a) {
    asm volatile("ldmatrix.sync.aligned.m8n8.x4.shared.b16 {%0,%1,%2,%3}, [%4];"
                 : "=r"(r0), "=r"(r1), "=r"(r2), "=r"(r3) : "r"(a));
}
// f16 MMA with f16 accumulate: C fragment = 2 packed f16x2 regs.
__device__ __forceinline__ void mma_h(uint32_t* d, const uint32_t* a,
                                      uint32_t b0, uint32_t b1) {
    asm volatile("mma.sync.aligned.m16n8k16.row.col.f16.f16.f16.f16 "
                 "{%0,%1}, {%2,%3,%4,%5}, {%6,%7}, {%0,%1};"
                 : "+r"(d[0]), "+r"(d[1])
                 : "r"(a[0]), "r"(a[1]), "r"(a[2]), "r"(a[3]), "r"(b0), "r"(b1));
}
__device__ __forceinline__ uint32_t pkh(float a, float b) {
    __half2 h = __floats2half2_rn(a, b);
    return *reinterpret_cast<uint32_t*>(&h);
}
__device__ __forceinline__ uint32_t hmax2u(uint32_t a, uint32_t b) {
    __half2 r = __hmax2(*reinterpret_cast<__half2*>(&a),
                        *reinterpret_cast<__half2*>(&b));
    return *reinterpret_cast<uint32_t*>(&r);
}

struct ChunkD {
    int ti, tj0, len, verA, verB, b;
    bool sym, edgeMode;
};
__device__ __forceinline__ ChunkD decode_chunk(unsigned c) {
    ChunkD d;
    if (c < 960u) {
        int seg = c >> 2, q = c & 3;
        d.b = seg / 30; d.ti = seg - d.b * 30;
        d.tj0 = q * 8; d.len = (q < 3) ? 8 : 6;
        d.sym = false; d.edgeMode = false; d.verA = 0; d.verB = 3;
    } else if (c < 2112u) {
        int dd = (int)c - 960;
        int g = dd / 72;
        int r = dd - g * 72;
        int kind = g >> 3; d.b = g & 7;
        int ti, tj0;
        if (r < 8)       { ti = r;              tj0 = 0; }
        else if (r < 24) { int q = r - 8;  ti = 8  + (q >> 1); tj0 = (q & 1) * 8; }
        else if (r < 48) { int q = r - 24; int qd = q / 3; ti = 16 + qd; tj0 = (q - qd * 3) * 8; }
        else             { int q = r - 48; ti = 24 + (q >> 2); tj0 = (q & 3) * 8; }
        d.ti = ti; d.tj0 = tj0;
        d.len = min(8, ti + 1 - tj0);
        d.sym = true; d.edgeMode = false; d.verA = kind; d.verB = 2 + kind;
    } else if (c < 2176u) {
        // xy edge strips: strip0 A=x[30] vs y tiles 0..30; strip1 A=y[30] vs x 0..29
        int dd = (int)c - 2112;
        d.b = dd >> 3;
        int e = dd & 7;
        int strip = e >> 2, q = e & 3;
        d.tj0 = q * 8;
        d.len = (q < 3) ? 8 : (strip == 0 ? 7 : 6);
        d.verA = strip ? 1 : 0; d.verB = strip ? 2 : 3;
        d.ti = NTILES - 1;
        d.sym = false; d.edgeMode = true;
    } else {
        // sym edge: ti=30 strip, tj 0..30
        int dd = (int)c - 2176;
        int g = dd >> 2, q = dd & 3;
        int kind = g >> 3; d.b = g & 7;
        d.verA = kind; d.verB = 2 + kind;
        d.tj0 = q * 8; d.len = (q < 3) ? 8 : 7;
        d.ti = NTILES - 1;
        d.sym = true; d.edgeMode = true;
    }
    return d;
}

extern __shared__ __align__(1024) char dsm[];

__global__ void __launch_bounds__(256, 2)
mmd_fused(const float* __restrict__ x, const float* __restrict__ y,
          float* __restrict__ out) {
    const int tid = threadIdx.x;
    const int wid = tid >> 5;
    const int lane = tid & 31;

    float* red = reinterpret_cast<float*>(dsm + SMEM_RED_OFF);
    unsigned int* tkt = reinterpret_cast<unsigned int*>(dsm + SMEM_TKT_OFF);
    unsigned int* lst = reinterpret_cast<unsigned int*>(dsm + SMEM_LST_OFF);

    const float K1f = 4.9479492581208223f;        // log2e / 0.2916
    const float C2f = 9.8958985162416446f;        // 2*log2e / 0.2916

    // ================= Phase 1: stage f16 operand rows =================
    {
        int gtid = blockIdx.x * 256 + tid;
        if (gtid < STAGE_TASKS) {
            int n = gtid % NROWS;
            int t2 = gtid / NROWS;
            int b = t2 & 7;
            int img = t2 >> 3;
            const float* im = img ? y : x;

            float rv[27];
            float u = 0.0f;
            bool valid = (n < NPATCH);
            if (valid) {
                int i = n / 62;
                int j = n - i * 62;
                const float* p = im + b * 12288 + (i << 6) + j;
                float sq = 0.0f;
                #pragma unroll
                for (int c = 0; c < 3; c++)
                    #pragma unroll
                    for (int rr = 0; rr < 3; rr++)
                        #pragma unroll
                        for (int ss = 0; ss < 3; ss++) {
                            float v = p[c * 4096 + (rr << 6) + ss];
                            sq = fmaf(v, v, sq);
                            rv[c * 9 + rr * 3 + ss] = v;
                        }
                u = sq * K1f;
            } else {
                #pragma unroll
                for (int k = 0; k < 27; k++) rv[k] = 0.0f;
            }
            uint32_t sw = (uint32_t)(n >> 1) & 3u;

            #pragma unroll
            for (int form = 0; form < 2; form++) {
                float rowv[32];
                #pragma unroll
                for (int k = 0; k < 27; k++)
                    rowv[k] = form ? rv[k] : (C2f * rv[k]);
                float nu = valid ? -u : -60000.0f;   // fp16-range pad sentinel
                if (form) { rowv[27] = nu;   rowv[28] = 1.0f; }
                else      { rowv[27] = 1.0f; rowv[28] = nu;   }
                rowv[29] = rowv[30] = rowv[31] = 0.0f;
                uint32_t wds[16];
                #pragma unroll
                for (int q = 0; q < 16; q++)
                    wds[q] = pkh(rowv[2*q], rowv[2*q+1]);
                int ver = form * 2 + img;
                int base = ((ver * BATCH + b) * NROWS + n) * ROW_U4;
                #pragma unroll
                for (int c = 0; c < 4; c++)
                    g_stage[base + (c ^ sw)] =
                        make_uint4(wds[4*c], wds[4*c+1], wds[4*c+2], wds[4*c+3]);
            }
        }
        __threadfence();
        __syncthreads();
        if (tid == 0) {
            atomicAdd(&g_bar1, 1u);
            unsigned int v;
            do {
                asm volatile("ld.acquire.gpu.global.u32 %0, [%1];"
                             : "=r"(v) : "l"(&g_bar1));
                if (v >= WORKERS) break;
                __nanosleep(64);
            } while (true);
        }
        __syncthreads();
        __threadfence();
    }

    // ================= Phase 2: pipelined persistent tile loop =================
    const int mg = wid & 3;          // A rows mg*32..+31
    const int ng = wid >> 2;         // B rows ng*64..+63
    const uint32_t a_base = smem_to_u32(dsm) + SMEM_A_OFF;    // 2 x 8192
    const uint32_t b_ring = smem_to_u32(dsm) + SMEM_B_OFF;    // 8 x 8192

    uint32_t offA[2][2];
    #pragma unroll
    for (int mt = 0; mt < 2; mt++)
        #pragma unroll
        for (int k = 0; k < 2; k++) {
            int rowA = mg * 32 + mt * 16 + (lane & 15);
            int ch = k * 2 + (lane >> 4);
            int swz = ch ^ ((rowA >> 1) & 3);
            offA[mt][k] = (uint32_t)(rowA * 64 + swz * 16);
        }
    uint32_t offB[2];
    #pragma unroll
    for (int k = 0; k < 2; k++) {
        int rloc = (lane & 7) + ((lane >> 4) << 3);
        int rowB = ng * 64 + rloc;
        int ch = k * 2 + ((lane >> 3) & 1);
        int swz = ch ^ ((rowB >> 1) & 3);
        offB[k] = (uint32_t)(rowB * 64 + swz * 16);
    }

    float s = 0.0f;
    uint32_t af[2][2][4];

    // ---- interior tile: EXACT R13/R16 hot body ----
    auto compute_tile = [&](int slot, int ti, int tj, bool sym) {
        const uint32_t bb = b_ring + (uint32_t)(slot * 8192);
        uint32_t acc[2][8][2];
        #pragma unroll
        for (int mt = 0; mt < 2; mt++)
            #pragma unroll
            for (int nt = 0; nt < 8; nt++)
                acc[mt][nt][0] = acc[mt][nt][1] = 0u;

        #pragma unroll
        for (int k = 0; k < 2; k++)
            #pragma unroll
            for (int p = 0; p < 4; p++) {
                uint32_t b0, b1, b2, b3;
                ldsm_x4(b0, b1, b2, b3, bb + offB[k] + (uint32_t)(p * 1024));
                mma_h(acc[0][2*p],   af[0][k], b0, b1);
                mma_h(acc[0][2*p+1], af[0][k], b2, b3);
                mma_h(acc[1][2*p],   af[1][k], b0, b1);
                mma_h(acc[1][2*p+1], af[1][k], b2, b3);
            }

        bool diagTile = sym && (tj == ti);

        uint32_t m16[16];
        #pragma unroll
        for (int mt = 0; mt < 2; mt++)
            #pragma unroll
            for (int nt = 0; nt < 8; nt++)
                m16[mt * 8 + nt] = hmax2u(acc[mt][nt][0], acc[mt][nt][1]);
        #pragma unroll
        for (int st = 8; st > 0; st >>= 1)
            #pragma unroll
            for (int i2 = 0; i2 < 8; i2++)
                if (i2 < st) m16[i2] = hmax2u(m16[i2], m16[i2 + st]);
        __half2 hm = *reinterpret_cast<__half2*>(&m16[0]);
        float mx = fmaxf(__low2float(hm), __high2float(hm));

        if (diagTile || __any_sync(0xffffffffu, mx > -30.0f)) {
            float w = sym ? ((tj == ti) ? 1.0f : 2.0f) : -2.0f;
            int rbase = mg * 32 + (lane >> 2);
            int cbase = ng * 64 + ((lane & 3) << 1);
            float ts = 0.0f;
            #pragma unroll
            for (int mt = 0; mt < 2; mt++)
                #pragma unroll
                for (int nt = 0; nt < 8; nt++)
                    #pragma unroll
                    for (int r = 0; r < 2; r++) {
                        int rl = rbase + mt * 16 + (r << 3);
                        __half2 hv = *reinterpret_cast<__half2*>(&acc[mt][nt][r]);
                        float a0 = __low2float(hv);
                        float a1 = __high2float(hv);
                        int cl0 = cbase + nt * 8;
                        bool d0 = diagTile && (rl == cl0);   // interior rows all valid
                        bool d1 = diagTile && (rl == cl0 + 1);
                        float e0, e1;
                        asm("ex2.approx.ftz.f32 %0, %1;" : "=f"(e0) : "f"(a0));
                        asm("ex2.approx.ftz.f32 %0, %1;" : "=f"(e1) : "f"(a1));
                        ts += (d0 ? 1.0f : e0) + (d1 ? 1.0f : e1);
                    }
            s = fmaf(w, ts, s);
        }
    };

    // ---- edge tile (A tile index 30, 4 valid rows): mg==0 warps only ----
    auto compute_edge = [&](int slot, int tj, bool symE) {
        if (mg != 0) return;
        bool colE = (tj == NTILES - 1);
        if (colE && ng != 0) return;
        const uint32_t bb = b_ring + (uint32_t)(slot * 8192);
        uint32_t acc[8][2];
        int ntN = colE ? 1 : 8;
        for (int nt = 0; nt < ntN; nt++) acc[nt][0] = acc[nt][1] = 0u;

        for (int k = 0; k < 2; k++) {
            int pN = colE ? 1 : 4;
            for (int p = 0; p < pN; p++) {
                uint32_t b0, b1, b2, b3;
                ldsm_x4(b0, b1, b2, b3, bb + offB[k] + (uint32_t)(p * 1024));
                mma_h(acc[2*p], af[0][k], b0, b1);
                if (!colE) mma_h(acc[2*p+1], af[0][k], b2, b3);
            }
        }

        bool diagTile = symE && colE;        // ti==tj==30
        uint32_t mT = acc[0][0];
        for (int nt = 0; nt < ntN; nt++) {
            mT = hmax2u(mT, acc[nt][0]);
            mT = hmax2u(mT, acc[nt][1]);
        }
        __half2 hm = *reinterpret_cast<__half2*>(&mT);
        float mx = fmaxf(__low2float(hm), __high2float(hm));

        if (diagTile || __any_sync(0xffffffffu, mx > -30.0f)) {
            float w = symE ? (colE ? 1.0f : 2.0f) : -2.0f;
            int rbase = (lane >> 2);
            int cbase = ng * 64 + ((lane & 3) << 1);
            float ts = 0.0f;
            for (int nt = 0; nt < ntN; nt++)
                for (int r = 0; r < 2; r++) {
                    int rl = rbase + (r << 3);
                    __half2 hv = *reinterpret_cast<__half2*>(&acc[nt][r]);
                    float a0 = __low2float(hv);
                    float a1 = __high2float(hv);
                    int cl0 = cbase + nt * 8;
                    bool ok = (rl < 4);      // 3840 + rl < 3844
                    bool d0 = diagTile && ok && (rl == cl0);
                    bool d1 = diagTile && ok && (rl == cl0 + 1);
                    float e0, e1;
                    asm("ex2.approx.ftz.f32 %0, %1;" : "=f"(e0) : "f"(a0));
                    asm("ex2.approx.ftz.f32 %0, %1;" : "=f"(e1) : "f"(a1));
                    ts += (d0 ? 1.0f : e0) + (d1 ? 1.0f : e1);
                }
            s = fmaf(w, ts, s);
        }
    };

    auto loadB = [&](const uint4* bbase, int tj0b, int cnt, int slot0) {
        for (int t = 0; t < cnt; t++) {
            const uint4* bs = bbase + ((tj0b + t) * TILE) * ROW_U4;
            uint32_t dst = b_ring + (uint32_t)((slot0 + t) * 8192);
            cp_async16(dst + (uint32_t)(tid * 16), bs + tid);
            cp_async16(dst + (uint32_t)((tid + 256) * 16), bs + tid + 256);
        }
    };
    auto loadA = [&](int verA, int b, int ti, int buf) {
        const uint4* asrc = g_stage + ((verA * BATCH + b) * NROWS + ti * TILE) * ROW_U4;
        uint32_t adst = a_base + (uint32_t)(buf * 8192);
        cp_async16(adst + (uint32_t)(tid * 16), asrc + tid);
        cp_async16(adst + (uint32_t)((tid + 256) * 16), asrc + tid + 256);
    };

    // ---- pipeline prologue: fetch two tickets, issue first chunk's loads ----
    if (tid == 0) {
        tkt[0] = atomicAdd(&g_ticket, 1u);
        tkt[1] = atomicAdd(&g_ticket, 1u);
    }
    __syncthreads();
    unsigned c = tkt[0];
    int tpar = 1, grp = 0, abuf = 0;
    ChunkD D;
    if (c < CHUNKS) {
        D = decode_chunk(c);
        loadA(D.verA, D.b, D.ti, abuf);
        const uint4* bb0 = g_stage + ((D.verB * BATCH + D.b) * NROWS) * ROW_U4;
        loadB(bb0, D.tj0, min(D.len, 4), grp * 4);
        CP_COMMIT();
    }

    while (c < CHUNKS) {
        const uint4* bbase = g_stage + ((D.verB * BATCH + D.b) * NROWS) * ROW_U4;
        int nw = (D.len + 3) >> 2;
        unsigned nxt = 0xFFFFFFFFu;
        for (int w = 0; w < nw; w++) {
            CP_WAIT0();
            __syncthreads();                 // window data visible; prev group free
            int myg = grp;
            grp ^= 1;
            if (w == 0) {
                nxt = tkt[tpar];             // published by the sync above
                uint32_t ab = a_base + (uint32_t)(abuf * 8192);
                #pragma unroll
                for (int mt = 0; mt < 2; mt++)
                    #pragma unroll
                    for (int k = 0; k < 2; k++)
                        ldsm_x4(af[mt][k][0], af[mt][k][1], af[mt][k][2], af[mt][k][3],
                                ab + offA[mt][k]);
                if (nw == 2) {
                    loadB(bbase, D.tj0 + 4, D.len - 4, grp * 4);
                    CP_COMMIT();
                }
            }
            if (w == nw - 1 && nxt < CHUNKS) {
                // prefetch next chunk (A -> other buffer, B -> next group)
                ChunkD N = decode_chunk(nxt);
                loadA(N.verA, N.b, N.ti, abuf ^ 1);
                const uint4* nb = g_stage + ((N.verB * BATCH + N.b) * NROWS) * ROW_U4;
                loadB(nb, N.tj0, min(N.len, 4), grp * 4);
                CP_COMMIT();
                if (tid == 0) tkt[tpar ^ 1] = atomicAdd(&g_ticket, 1u);
            }
            int s0 = myg * 4;
            int w0 = w * 4;
            int rem = D.len - w0;
            if (!D.edgeMode) {
                if (rem >= 4) {              // straight-line 4 tiles for ILP
                    compute_tile(s0,     D.ti, D.tj0 + w0,     D.sym);
                    compute_tile(s0 + 1, D.ti, D.tj0 + w0 + 1, D.sym);
                    compute_tile(s0 + 2, D.ti, D.tj0 + w0 + 2, D.sym);
                    compute_tile(s0 + 3, D.ti, D.tj0 + w0 + 3, D.sym);
                } else {
                    for (int t = 0; t < rem; t++)
                        compute_tile(s0 + t, D.ti, D.tj0 + w0 + t, D.sym);
                }
            } else {
                int n4 = rem < 4 ? rem : 4;
                for (int t = 0; t < n4; t++)
                    compute_edge(s0 + t, D.tj0 + w0 + t, D.sym);
            }
        }
        if (nxt < CHUNKS) {
            c = nxt;
            D = decode_chunk(c);
            tpar ^= 1;
            abuf ^= 1;
        } else {
            break;
        }
    }

    // ================= Phase 3: reduce + finalize =================
    #pragma unroll
    for (int o = 16; o; o >>= 1) s += __shfl_xor_sync(0xffffffffu, s, o);
    if (lane == 0) red[wid] = s;
    __syncthreads();
    if (tid == 0) {
        float tot = 0.0f;
        #pragma unroll
        for (int i2 = 0; i2 < 8; i2++) tot += red[i2];
        g_partials[blockIdx.x] = tot;
        __threadfence();
        unsigned int old = atomicAdd(&g_done, 1u);
        *lst = (old == WORKERS - 1) ? 1u : 0u;
    }
    __syncthreads();
    if (*lst) {
        __threadfence();
        float v = 0.0f;
        for (int i = tid; i < WORKERS; i += 256) v += g_partials[i];
        #pragma unroll
        for (int o = 16; o; o >>= 1) v += __shfl_xor_sync(0xffffffffu, v, o);
        if (lane == 0) red[wid] = v;
        __syncthreads();
        if (tid == 0) {
            float tot = 0.0f;
            #pragma unroll
            for (int i2 = 0; i2 < 8; i2++) tot += red[i2];
            out[0] = tot * (float)(1.0 / (8.0 * 3844.0 * 3844.0));
            g_bar1 = 0u;
            g_ticket = 0u;
            __threadfence();
            g_done = 0u;
        }
    }
}

extern "C" void kernel_launch(void* const* d_in, const int* in_sizes, int n_in,
                              void* d_out, int out_size) {
    const float* x = (const float*)d_in[0];
    const float* y = (const float*)d_in[1];
    cudaFuncSetAttribute(mmd_fused,
                         cudaFuncAttributeMaxDynamicSharedMemorySize, SMEM_BYTES);
    mmd_fused<<<WORKERS, 256, SMEM_BYTES>>>(x, y, (float*)d_out);
}